// round 3
// baseline (speedup 1.0000x reference)
#include <cuda_runtime.h>

// Lower-triangular matvec: y[i] = sum_{j<=i} W[i,j] * x[j]
// n = 8192, W row-major fp32 (lower triangle = 128 MB, streamed once).
//
// R3: One block per row PAIR (i, n-1-i) -> every block reads exactly n+1
// W-elements (perfect balance). x (32 KB) is staged into shared memory once
// per block, so the streaming loop issues ONLY W global loads (4x unrolled
// LDG.128, __ldcs evict-first) plus LDS.128 for x — doubling W-load dispatch
// density at the LSU vs R2 where x-LDGs consumed half the slots.

#define NTHREADS 256
#define N_MAX 8192

__device__ __forceinline__ float dot4(float4 w, float4 v) {
    return w.x * v.x + w.y * v.y + w.z * v.z + w.w * v.w;
}

// Partial dot of one W row (length len) with shared-memory x.
__device__ __forceinline__ float row_dot(const float* __restrict__ Wr,
                                         const float4* __restrict__ xs4,
                                         const float* __restrict__ xs,
                                         int len, int tid)
{
    const float4* __restrict__ W4 = reinterpret_cast<const float4*>(Wr);
    const int nv4 = len >> 2;

    float a0 = 0.0f, a1 = 0.0f, a2 = 0.0f, a3 = 0.0f;

    int k = tid;
    // Main stream: 4 independent LDG.128 (W) in flight per thread;
    // x comes from shared memory (no LSU global-dispatch contention).
    for (; k + 3 * NTHREADS < nv4; k += 4 * NTHREADS) {
        float4 w0 = __ldcs(W4 + k);
        float4 w1 = __ldcs(W4 + k + NTHREADS);
        float4 w2 = __ldcs(W4 + k + 2 * NTHREADS);
        float4 w3 = __ldcs(W4 + k + 3 * NTHREADS);
        float4 v0 = xs4[k];
        float4 v1 = xs4[k + NTHREADS];
        float4 v2 = xs4[k + 2 * NTHREADS];
        float4 v3 = xs4[k + 3 * NTHREADS];
        a0 += dot4(w0, v0);
        a1 += dot4(w1, v1);
        a2 += dot4(w2, v2);
        a3 += dot4(w3, v3);
    }
    #pragma unroll 1
    for (; k < nv4; k += NTHREADS) {
        a0 += dot4(__ldcs(W4 + k), xs4[k]);
    }

    float acc = (a0 + a1) + (a2 + a3);

    // Scalar tail (len % 4 elements).
    const int tail = len & 3;
    if (tid < tail) {
        const int j = (nv4 << 2) + tid;
        acc += Wr[j] * xs[j];
    }
    return acc;
}

__global__ __launch_bounds__(NTHREADS)
void tril_mv_kernel(const float* __restrict__ x,
                    const float* __restrict__ W,
                    float* __restrict__ y,
                    int n)
{
    __shared__ float xs[N_MAX];                 // 32 KB
    __shared__ float red0[NTHREADS / 32];
    __shared__ float red1[NTHREADS / 32];

    const int b   = blockIdx.x;      // 0 .. n/2-1
    const int tid = threadIdx.x;

    const int r0 = b;
    const int r1 = n - 1 - b;

    // Stage x into shared memory (coalesced float4 copy).
    {
        const float4* __restrict__ xg4 = reinterpret_cast<const float4*>(x);
        float4* xs4w = reinterpret_cast<float4*>(xs);
        const int nv4 = n >> 2;                 // 2048
        #pragma unroll
        for (int k = tid; k < nv4; k += NTHREADS) {
            xs4w[k] = xg4[k];
        }
    }
    __syncthreads();

    const float4* __restrict__ xs4 = reinterpret_cast<const float4*>(xs);

    float acc0 = row_dot(W + (size_t)r0 * n, xs4, xs, r0 + 1, tid);
    float acc1 = row_dot(W + (size_t)r1 * n, xs4, xs, r1 + 1, tid);

    // ---- dual block reduction ----
    #pragma unroll
    for (int off = 16; off > 0; off >>= 1) {
        acc0 += __shfl_down_sync(0xffffffffu, acc0, off);
        acc1 += __shfl_down_sync(0xffffffffu, acc1, off);
    }
    const int warp = tid >> 5;
    const int lane = tid & 31;
    if (lane == 0) {
        red0[warp] = acc0;
        red1[warp] = acc1;
    }
    __syncthreads();

    if (warp == 0) {
        float a0 = (lane < NTHREADS / 32) ? red0[lane] : 0.0f;
        float a1 = (lane < NTHREADS / 32) ? red1[lane] : 0.0f;
        #pragma unroll
        for (int off = (NTHREADS / 64); off > 0; off >>= 1) {
            a0 += __shfl_down_sync(0xffffffffu, a0, off);
            a1 += __shfl_down_sync(0xffffffffu, a1, off);
        }
        if (lane == 0) {
            y[r0] = a0;
            y[r1] = a1;
        }
    }
}

extern "C" void kernel_launch(void* const* d_in, const int* in_sizes, int n_in,
                              void* d_out, int out_size) {
    const float* x = (const float*)d_in[0];   // [n]
    const float* W = (const float*)d_in[1];   // [n, n] row-major
    float*       y = (float*)d_out;           // [n]

    const int n = in_sizes[0];                // 8192 (even)

    tril_mv_kernel<<<n / 2, NTHREADS>>>(x, W, y, n);
}

// round 4
// speedup vs baseline: 1.2266x; 1.2266x over previous
#include <cuda_runtime.h>

// Lower-triangular matvec: y[i] = sum_{j<=i} W[i,j] * x[j]
// n = 8192, W row-major fp32 (lower triangle = 128 MB, streamed once).
//
// R4: one block per ROW, scheduled longest-first (block b -> row n-1-b).
// Monotonically decreasing block cost packs the tail perfectly (greedy
// scheduling), eliminating the ~8.5% wave-quantization loss of the
// equal-cost pair-block layout. Inner loop: 4x unrolled LDG.128 on W
// (__ldcs, read-once) + x via read-only path (L1-resident, 32 KB).

#define NTHREADS 256

__device__ __forceinline__ float dot4(float4 w, float4 v) {
    return w.x * v.x + w.y * v.y + w.z * v.z + w.w * v.w;
}

__global__ __launch_bounds__(NTHREADS)
void tril_mv_kernel(const float* __restrict__ x,
                    const float* __restrict__ W,
                    float* __restrict__ y,
                    int n)
{
    __shared__ float red[NTHREADS / 32];

    const int tid = threadIdx.x;
    const int r   = n - 1 - blockIdx.x;       // longest rows get lowest bids
    const int len = r + 1;

    const float4* __restrict__ x4 = reinterpret_cast<const float4*>(x);
    const float4* __restrict__ W4 =
        reinterpret_cast<const float4*>(W + (size_t)r * n);

    const int nv4 = len >> 2;

    float a0 = 0.0f, a1 = 0.0f, a2 = 0.0f, a3 = 0.0f;

    int k = tid;
    // Main stream: 4 independent LDG.128 (W) + 4 x-loads (L1 hits) in flight.
    for (; k + 3 * NTHREADS < nv4; k += 4 * NTHREADS) {
        float4 w0 = __ldcs(W4 + k);
        float4 w1 = __ldcs(W4 + k + NTHREADS);
        float4 w2 = __ldcs(W4 + k + 2 * NTHREADS);
        float4 w3 = __ldcs(W4 + k + 3 * NTHREADS);
        float4 v0 = __ldg(x4 + k);
        float4 v1 = __ldg(x4 + k + NTHREADS);
        float4 v2 = __ldg(x4 + k + 2 * NTHREADS);
        float4 v3 = __ldg(x4 + k + 3 * NTHREADS);
        a0 += dot4(w0, v0);
        a1 += dot4(w1, v1);
        a2 += dot4(w2, v2);
        a3 += dot4(w3, v3);
    }
    #pragma unroll 1
    for (; k < nv4; k += NTHREADS) {
        a0 += dot4(__ldcs(W4 + k), __ldg(x4 + k));
    }

    float acc = (a0 + a1) + (a2 + a3);

    // Scalar tail (len % 4 elements).
    const int tail = len & 3;
    if (tid < tail) {
        const int j = (nv4 << 2) + tid;
        acc += W[(size_t)r * n + j] * x[j];
    }

    // ---- block reduction ----
    #pragma unroll
    for (int off = 16; off > 0; off >>= 1) {
        acc += __shfl_down_sync(0xffffffffu, acc, off);
    }
    const int warp = tid >> 5;
    const int lane = tid & 31;
    if (lane == 0) red[warp] = acc;
    __syncthreads();

    if (warp == 0) {
        float a = (lane < NTHREADS / 32) ? red[lane] : 0.0f;
        #pragma unroll
        for (int off = (NTHREADS / 64); off > 0; off >>= 1) {
            a += __shfl_down_sync(0xffffffffu, a, off);
        }
        if (lane == 0) y[r] = a;
    }
}

extern "C" void kernel_launch(void* const* d_in, const int* in_sizes, int n_in,
                              void* d_out, int out_size) {
    const float* x = (const float*)d_in[0];   // [n]
    const float* W = (const float*)d_in[1];   // [n, n] row-major
    float*       y = (float*)d_out;           // [n]

    const int n = in_sizes[0];                // 8192

    tril_mv_kernel<<<n, NTHREADS>>>(x, W, y, n);
}